// round 7
// baseline (speedup 1.0000x reference)
#include <cuda_runtime.h>
#include <math.h>
#include <stdint.h>

#define Dm 1024
#define Hh 16
#define HDm 64
#define FFm 4096
#define BATCHm 8
#define SEQm 1024
#define TOKm (BATCHm*SEQm)   /* 8192 */
#define BHm (BATCHm*Hh)      /* 128  */

static __device__ float g_h   [(size_t)TOKm*Dm];        // LN outputs (reused)
static __device__ float g_q   [(size_t)BHm*SEQm*HDm];
static __device__ float g_k   [(size_t)BHm*SEQm*HDm];
static __device__ float g_v   [(size_t)BHm*SEQm*HDm];
static __device__ float g_o   [(size_t)TOKm*Dm];        // attn output [b,t,(h,hd)]
static __device__ float g_x1  [(size_t)TOKm*Dm];        // after attn residual
static __device__ float g_g   [(size_t)TOKm*FFm];       // gelu(fc1) out

// ---------------------------------------------------------------------------
// helpers
// ---------------------------------------------------------------------------
__device__ __forceinline__ uint32_t f2tf32(float f) {
    uint32_t r;
    asm("cvt.rna.tf32.f32 %0, %1;" : "=r"(r) : "f"(f));
    return r;
}
__device__ __forceinline__ void cp16(uint32_t dst, const void* src) {
    asm volatile("cp.async.cg.shared.global [%0], [%1], 16;" :: "r"(dst), "l"(src));
}
__device__ __forceinline__ void mma_tf32(float* c, const uint32_t* a, const uint32_t* b) {
    asm volatile(
        "mma.sync.aligned.m16n8k8.row.col.f32.tf32.tf32.f32 "
        "{%0,%1,%2,%3},{%4,%5,%6,%7},{%8,%9},{%0,%1,%2,%3};"
        : "+f"(c[0]), "+f"(c[1]), "+f"(c[2]), "+f"(c[3])
        : "r"(a[0]), "r"(a[1]), "r"(a[2]), "r"(a[3]), "r"(b[0]), "r"(b[1]));
}

// ---------------------------------------------------------------------------
// LayerNorm: one block per row (D=1024), 256 threads.
// ---------------------------------------------------------------------------
__global__ void ln_kernel(const float* __restrict__ x,
                          const float* __restrict__ gam,
                          const float* __restrict__ bet,
                          float* __restrict__ out)
{
    const float* xr = x + (size_t)blockIdx.x * Dm;
    float* orow     = out + (size_t)blockIdx.x * Dm;
    int tid = threadIdx.x;

    float s = 0.f, s2 = 0.f;
    for (int i = tid; i < Dm; i += 256) {
        float v = xr[i];
        s += v; s2 += v * v;
    }
    __shared__ float rs[8], rs2[8];
    #pragma unroll
    for (int o = 16; o > 0; o >>= 1) {
        s  += __shfl_xor_sync(0xffffffffu, s,  o);
        s2 += __shfl_xor_sync(0xffffffffu, s2, o);
    }
    if ((tid & 31) == 0) { rs[tid >> 5] = s; rs2[tid >> 5] = s2; }
    __syncthreads();
    if (tid < 32) {
        float a = (tid < 8) ? rs[tid]  : 0.f;
        float b = (tid < 8) ? rs2[tid] : 0.f;
        #pragma unroll
        for (int o = 4; o > 0; o >>= 1) {
            a += __shfl_xor_sync(0xffffffffu, a, o);
            b += __shfl_xor_sync(0xffffffffu, b, o);
        }
        if (tid == 0) { rs[0] = a; rs2[0] = b; }
    }
    __syncthreads();
    float mu  = rs[0] * (1.0f / Dm);
    float var = rs2[0] * (1.0f / Dm) - mu * mu;
    float inv = rsqrtf(var + 1e-5f);
    for (int i = tid; i < Dm; i += 256)
        orow[i] = (xr[i] - mu) * inv * gam[i] + bet[i];
}

// ---------------------------------------------------------------------------
// Flash attention: one block = 128 q-rows of one (b,h); 8 warps x 16 rows.
// Q pre-scaled (0.125) and biased at qkv scatter. Iterates 16 K/V tiles of 64.
// Never materializes the score matrix. Writes O directly in [b,t,(h,hd)].
// ---------------------------------------------------------------------------
__global__ __launch_bounds__(256)
void flash_kernel(const float* __restrict__ Q, const float* __restrict__ K,
                  const float* __restrict__ V, float* __restrict__ O)
{
    __shared__ float Ks[64][68];
    __shared__ float Vs[64][68];

    int tid = threadIdx.x, lane = tid & 31, warp = tid >> 5;
    int g = lane >> 2, tg = lane & 3;
    int bh = blockIdx.y;
    int qrow0 = blockIdx.x * 128 + warp * 16;
    const float* Qb = Q + (size_t)bh * SEQm * HDm;
    const float* Kb = K + (size_t)bh * SEQm * HDm;
    const float* Vb = V + (size_t)bh * SEQm * HDm;

    // Q tile -> tf32 A-fragments (16 rows per warp, K=64 in 8 chunks)
    uint32_t aq[8][4];
    #pragma unroll
    for (int kk = 0; kk < 8; kk++) {
        aq[kk][0] = f2tf32(Qb[(size_t)(qrow0 + g    ) * HDm + kk * 8 + tg    ]);
        aq[kk][1] = f2tf32(Qb[(size_t)(qrow0 + g + 8) * HDm + kk * 8 + tg    ]);
        aq[kk][2] = f2tf32(Qb[(size_t)(qrow0 + g    ) * HDm + kk * 8 + tg + 4]);
        aq[kk][3] = f2tf32(Qb[(size_t)(qrow0 + g + 8) * HDm + kk * 8 + tg + 4]);
    }

    float acc_o[8][4] = {};
    float m0 = -3.4e38f, m1 = -3.4e38f;
    float l0 = 0.f, l1 = 0.f;

    for (int jt = 0; jt < SEQm / 64; jt++) {
        // stage K/V tile [64,64] into smem
        #pragma unroll
        for (int i = tid; i < 64 * 16; i += 256) {
            int r = i >> 4, c4 = i & 15;
            *(float4*)&Ks[r][c4 * 4] =
                *(const float4*)(Kb + (size_t)(jt * 64 + r) * HDm + c4 * 4);
            *(float4*)&Vs[r][c4 * 4] =
                *(const float4*)(Vb + (size_t)(jt * 64 + r) * HDm + c4 * 4);
        }
        __syncthreads();

        // S = Q @ K^T  (warp: 16 x 64)
        float acc_s[8][4] = {};
        #pragma unroll
        for (int kk = 0; kk < 8; kk++) {
            #pragma unroll
            for (int ni = 0; ni < 8; ni++) {
                uint32_t bf[2];
                bf[0] = f2tf32(Ks[ni * 8 + g][kk * 8 + tg    ]);
                bf[1] = f2tf32(Ks[ni * 8 + g][kk * 8 + tg + 4]);
                mma_tf32(acc_s[ni], aq[kk], bf);
            }
        }

        // online softmax (rows g and g+8; row spread over the 4 quad lanes)
        float tm0 = -3.4e38f, tm1 = -3.4e38f;
        #pragma unroll
        for (int ni = 0; ni < 8; ni++) {
            tm0 = fmaxf(tm0, fmaxf(acc_s[ni][0], acc_s[ni][1]));
            tm1 = fmaxf(tm1, fmaxf(acc_s[ni][2], acc_s[ni][3]));
        }
        tm0 = fmaxf(tm0, __shfl_xor_sync(0xffffffffu, tm0, 1));
        tm0 = fmaxf(tm0, __shfl_xor_sync(0xffffffffu, tm0, 2));
        tm1 = fmaxf(tm1, __shfl_xor_sync(0xffffffffu, tm1, 1));
        tm1 = fmaxf(tm1, __shfl_xor_sync(0xffffffffu, tm1, 2));
        float mn0 = fmaxf(m0, tm0), mn1 = fmaxf(m1, tm1);
        float sc0 = __expf(m0 - mn0), sc1 = __expf(m1 - mn1);
        m0 = mn0; m1 = mn1;

        float ls0 = 0.f, ls1 = 0.f;
        #pragma unroll
        for (int ni = 0; ni < 8; ni++) {
            acc_s[ni][0] = __expf(acc_s[ni][0] - mn0);
            acc_s[ni][1] = __expf(acc_s[ni][1] - mn0);
            acc_s[ni][2] = __expf(acc_s[ni][2] - mn1);
            acc_s[ni][3] = __expf(acc_s[ni][3] - mn1);
            ls0 += acc_s[ni][0] + acc_s[ni][1];
            ls1 += acc_s[ni][2] + acc_s[ni][3];
        }
        ls0 += __shfl_xor_sync(0xffffffffu, ls0, 1);
        ls0 += __shfl_xor_sync(0xffffffffu, ls0, 2);
        ls1 += __shfl_xor_sync(0xffffffffu, ls1, 1);
        ls1 += __shfl_xor_sync(0xffffffffu, ls1, 2);
        l0 = l0 * sc0 + ls0;
        l1 = l1 * sc1 + ls1;

        #pragma unroll
        for (int ni = 0; ni < 8; ni++) {
            acc_o[ni][0] *= sc0; acc_o[ni][1] *= sc0;
            acc_o[ni][2] *= sc1; acc_o[ni][3] *= sc1;
        }

        // O += P @ V : convert P acc-layout -> A-frag via quad shuffles
        int src0 = (lane & ~3) | (tg >> 1);
        int src1 = src0 ^ 2;
        bool odd = tg & 1;
        #pragma unroll
        for (int kk2 = 0; kk2 < 8; kk2++) {
            float p00 = __shfl_sync(0xffffffffu, acc_s[kk2][0], src0);
            float p01 = __shfl_sync(0xffffffffu, acc_s[kk2][1], src0);
            float p10 = __shfl_sync(0xffffffffu, acc_s[kk2][2], src0);
            float p11 = __shfl_sync(0xffffffffu, acc_s[kk2][3], src0);
            float r00 = __shfl_sync(0xffffffffu, acc_s[kk2][0], src1);
            float r01 = __shfl_sync(0xffffffffu, acc_s[kk2][1], src1);
            float r10 = __shfl_sync(0xffffffffu, acc_s[kk2][2], src1);
            float r11 = __shfl_sync(0xffffffffu, acc_s[kk2][3], src1);
            uint32_t ap[4];
            ap[0] = f2tf32(odd ? p01 : p00);   // P[g   ][kk2*8+tg  ]
            ap[1] = f2tf32(odd ? p11 : p10);   // P[g+8 ][kk2*8+tg  ]
            ap[2] = f2tf32(odd ? r01 : r00);   // P[g   ][kk2*8+tg+4]
            ap[3] = f2tf32(odd ? r11 : r10);   // P[g+8 ][kk2*8+tg+4]
            #pragma unroll
            for (int ni = 0; ni < 8; ni++) {
                uint32_t bv[2];
                bv[0] = f2tf32(Vs[kk2 * 8 + tg    ][ni * 8 + g]);
                bv[1] = f2tf32(Vs[kk2 * 8 + tg + 4][ni * 8 + g]);
                mma_tf32(acc_o[ni], ap, bv);
            }
        }
        __syncthreads();
    }

    // write O in [b, t, (h,hd)] row-major [TOK, D] layout used by proj GEMM
    int bb = bh >> 4, hh = bh & 15;
    float inv0 = 1.f / l0, inv1 = 1.f / l1;
    size_t base0 = ((size_t)bb * SEQm + blockIdx.x * 128 + warp * 16 + g) * Dm + hh * HDm;
    size_t base1 = base0 + (size_t)8 * Dm;
    #pragma unroll
    for (int ni = 0; ni < 8; ni++) {
        int c = ni * 8 + tg * 2;
        float2 w0 = make_float2(acc_o[ni][0] * inv0, acc_o[ni][1] * inv0);
        float2 w1 = make_float2(acc_o[ni][2] * inv1, acc_o[ni][3] * inv1);
        *(float2*)&O[base0 + c] = w0;
        *(float2*)&O[base1 + c] = w1;
    }
}

// ---------------------------------------------------------------------------
// tf32 tensor-core GEMM, cp.async double-buffered.
// C[M,N] = A[M,K] * B^T; B row-major [N,K].
// EPI: 2 bias+residual, 3 bias+exact-gelu, 5 qkv scatter (bias=qb, res=vb).
// ---------------------------------------------------------------------------
template<int BM, int BN, int BK, int WM, int WN, int EPI>
__global__ __launch_bounds__((BM/WM)*(BN/WN)*32)
void tgemm(const float* __restrict__ A, const float* __restrict__ B,
           float* __restrict__ C, int M, int N, int K,
           const float* __restrict__ bias, const float* __restrict__ res)
{
    constexpr int WARPS_M = BM / WM, WARPS_N = BN / WN;
    constexpr int NT = WARPS_M * WARPS_N * 32;
    constexpr int MI = WM / 16, NI = WN / 8, KI = BK / 8;
    constexpr int BKP = BK + 4;

    __shared__ float As[2][BM][BKP];
    __shared__ float Bs[2][BN][BKP];

    int tid = threadIdx.x, lane = tid & 31, warp = tid >> 5;
    int wm = (warp % WARPS_M) * WM, wn = (warp / WARPS_M) * WN;
    int m0 = blockIdx.y * BM, n0 = blockIdx.x * BN;

    uint32_t sA = (uint32_t)__cvta_generic_to_shared(&As[0][0][0]);
    uint32_t sB = (uint32_t)__cvta_generic_to_shared(&Bs[0][0][0]);

    auto loadTile = [&](int st, int k0) {
        for (int i = tid; i < BM * BK / 4; i += NT) {
            int r = i / (BK / 4), c = i % (BK / 4);
            uint32_t dst = sA + (uint32_t)(((st * BM + r) * BKP + c * 4) * 4);
            cp16(dst, A + (size_t)(m0 + r) * K + k0 + c * 4);
        }
        for (int i = tid; i < BN * BK / 4; i += NT) {
            int r = i / (BK / 4), c = i % (BK / 4);
            uint32_t dst = sB + (uint32_t)(((st * BN + r) * BKP + c * 4) * 4);
            cp16(dst, B + (size_t)(n0 + r) * K + k0 + c * 4);
        }
        asm volatile("cp.async.commit_group;");
    };

    float acc[MI][NI][4] = {};
    int g = lane >> 2, tg = lane & 3;

    loadTile(0, 0);
    int NKT = K / BK;
    for (int kt = 0; kt < NKT; kt++) {
        int cur = kt & 1;
        if (kt + 1 < NKT) {
            loadTile((kt + 1) & 1, (kt + 1) * BK);
            asm volatile("cp.async.wait_group 1;");
        } else {
            asm volatile("cp.async.wait_group 0;");
        }
        __syncthreads();

        #pragma unroll
        for (int kk = 0; kk < KI; kk++) {
            uint32_t af[MI][4];
            uint32_t bf[NI][2];
            #pragma unroll
            for (int mi = 0; mi < MI; mi++) {
                int r0 = wm + mi * 16 + g;
                af[mi][0] = f2tf32(As[cur][r0    ][kk * 8 + tg    ]);
                af[mi][1] = f2tf32(As[cur][r0 + 8][kk * 8 + tg    ]);
                af[mi][2] = f2tf32(As[cur][r0    ][kk * 8 + tg + 4]);
                af[mi][3] = f2tf32(As[cur][r0 + 8][kk * 8 + tg + 4]);
            }
            #pragma unroll
            for (int ni = 0; ni < NI; ni++) {
                int cc = wn + ni * 8 + g;
                bf[ni][0] = f2tf32(Bs[cur][cc][kk * 8 + tg    ]);
                bf[ni][1] = f2tf32(Bs[cur][cc][kk * 8 + tg + 4]);
            }
            #pragma unroll
            for (int mi = 0; mi < MI; mi++)
                #pragma unroll
                for (int ni = 0; ni < NI; ni++)
                    mma_tf32(acc[mi][ni], af[mi], bf[ni]);
        }
        __syncthreads();
    }

    // ---- epilogue ----
    #pragma unroll
    for (int mi = 0; mi < MI; mi++) {
        #pragma unroll
        for (int ni = 0; ni < NI; ni++) {
            #pragma unroll
            for (int half = 0; half < 2; half++) {
                int m = m0 + wm + mi * 16 + g + half * 8;
                float v0 = acc[mi][ni][half * 2 + 0];
                float v1 = acc[mi][ni][half * 2 + 1];
                int n = n0 + wn + ni * 8 + tg * 2;
                #pragma unroll
                for (int e = 0; e < 2; e++) {
                    float v = e ? v1 : v0;
                    int nn = n + e;
                    if (EPI == 2) {
                        C[(size_t)m * N + nn] = v + bias[nn] + res[(size_t)m * N + nn];
                    } else if (EPI == 3) {
                        float t = v + bias[nn];
                        C[(size_t)m * N + nn] =
                            0.5f * t * (1.f + erff(t * 0.70710678118654752f));
                    } else if (EPI == 5) {
                        int which = nn >> 10;
                        int r = nn & 1023;
                        int hh = r >> 6, hd = r & 63;
                        int bb = m >> 10, t = m & 1023;
                        size_t dst = (((size_t)bb * Hh + hh) * SEQm + t) * HDm + hd;
                        if (which == 0)      g_q[dst] = (v + bias[r]) * 0.125f;
                        else if (which == 1) g_k[dst] = v;
                        else                 g_v[dst] = v + res[r];
                    }
                }
            }
        }
    }
}

// ---------------------------------------------------------------------------
extern "C" void kernel_launch(void* const* d_in, const int* in_sizes, int n_in,
                              void* d_out, int out_size)
{
    const float* x      = (const float*)d_in[0];
    const float* ln1_g  = (const float*)d_in[1];
    const float* ln1_b  = (const float*)d_in[2];
    const float* ln2_g  = (const float*)d_in[3];
    const float* ln2_b  = (const float*)d_in[4];
    const float* qkv_w  = (const float*)d_in[5];
    const float* q_bias = (const float*)d_in[6];
    const float* v_bias = (const float*)d_in[7];
    const float* proj_w = (const float*)d_in[8];
    const float* proj_b = (const float*)d_in[9];
    const float* fc1_w  = (const float*)d_in[10];
    const float* fc1_b  = (const float*)d_in[11];
    const float* fc2_w  = (const float*)d_in[12];
    const float* fc2_b  = (const float*)d_in[13];
    float* out = (float*)d_out;

    float *h, *q, *k, *v, *o, *x1, *g;
    cudaGetSymbolAddress((void**)&h,  g_h);
    cudaGetSymbolAddress((void**)&q,  g_q);
    cudaGetSymbolAddress((void**)&k,  g_k);
    cudaGetSymbolAddress((void**)&v,  g_v);
    cudaGetSymbolAddress((void**)&o,  g_o);
    cudaGetSymbolAddress((void**)&x1, g_x1);
    cudaGetSymbolAddress((void**)&g,  g_g);

    // 1. LN1
    ln_kernel<<<TOKm, 256>>>(x, ln1_g, ln1_b, h);

    // 2. QKV = h @ qkv_w^T, fused scatter to q/k/v [B,H,N,HD] + biases + q-scale
    tgemm<128,128,16,64,32,5><<<dim3(3072/128, TOKm/128, 1), 256>>>(
        h, qkv_w, nullptr, TOKm, 3*Dm, Dm, q_bias, v_bias);

    // 3. flash attention -> o in [b,t,(h,hd)]
    flash_kernel<<<dim3(SEQm/128, BHm), 256>>>(q, k, v, o);

    // 4. x1 = x + o @ proj_w^T + proj_b
    tgemm<128,128,16,64,32,2><<<dim3(Dm/128, TOKm/128, 1), 256>>>(
        o, proj_w, x1, TOKm, Dm, Dm, proj_b, x);

    // 5. LN2
    ln_kernel<<<TOKm, 256>>>(x1, ln2_g, ln2_b, h);

    // 6. g = gelu(h @ fc1_w^T + fc1_b)
    tgemm<128,128,16,64,32,3><<<dim3(FFm/128, TOKm/128, 1), 256>>>(
        h, fc1_w, g, TOKm, FFm, Dm, fc1_b, nullptr);

    // 7. out = x1 + g @ fc2_w^T + fc2_b
    tgemm<128,128,16,64,32,2><<<dim3(Dm/128, TOKm/128, 1), 256>>>(
        g, fc2_w, out, TOKm, Dm, FFm, fc2_b, x1);
}

// round 8
// speedup vs baseline: 1.4428x; 1.4428x over previous
#include <cuda_runtime.h>
#include <math.h>
#include <stdint.h>

#define Dm 1024
#define Hh 16
#define HDm 64
#define FFm 4096
#define BATCHm 8
#define SEQm 1024
#define TOKm (BATCHm*SEQm)   /* 8192 */
#define BHm (BATCHm*Hh)      /* 128  */

static __device__ float g_h   [(size_t)TOKm*Dm];        // LN outputs (reused)
static __device__ float g_q   [(size_t)BHm*SEQm*HDm];
static __device__ float g_k   [(size_t)BHm*SEQm*HDm];
static __device__ float g_v   [(size_t)BHm*SEQm*HDm];
static __device__ float g_s   [(size_t)BHm*SEQm*SEQm]; // exp(scores)
static __device__ float g_o   [(size_t)TOKm*Dm];        // attn output [b,t,(h,hd)]
static __device__ float g_x1  [(size_t)TOKm*Dm];        // after attn residual
static __device__ float g_g   [(size_t)TOKm*FFm];       // gelu(fc1) out

// ---------------------------------------------------------------------------
// helpers
// ---------------------------------------------------------------------------
__device__ __forceinline__ uint32_t f2tf32(float f) {
    uint32_t r;
    asm("cvt.rna.tf32.f32 %0, %1;" : "=r"(r) : "f"(f));
    return r;
}
__device__ __forceinline__ void cp16(uint32_t dst, const void* src) {
    asm volatile("cp.async.cg.shared.global [%0], [%1], 16;" :: "r"(dst), "l"(src));
}
__device__ __forceinline__ void mma_tf32(float* c, const uint32_t* a, const uint32_t* b) {
    asm volatile(
        "mma.sync.aligned.m16n8k8.row.col.f32.tf32.tf32.f32 "
        "{%0,%1,%2,%3},{%4,%5,%6,%7},{%8,%9},{%0,%1,%2,%3};"
        : "+f"(c[0]), "+f"(c[1]), "+f"(c[2]), "+f"(c[3])
        : "r"(a[0]), "r"(a[1]), "r"(a[2]), "r"(a[3]), "r"(b[0]), "r"(b[1]));
}

// ---------------------------------------------------------------------------
// LayerNorm: one block per row (D=1024), 256 threads.
// ---------------------------------------------------------------------------
__global__ void ln_kernel(const float* __restrict__ x,
                          const float* __restrict__ gam,
                          const float* __restrict__ bet,
                          float* __restrict__ out)
{
    const float* xr = x + (size_t)blockIdx.x * Dm;
    float* orow     = out + (size_t)blockIdx.x * Dm;
    int tid = threadIdx.x;

    float s = 0.f, s2 = 0.f;
    for (int i = tid; i < Dm; i += 256) {
        float v = xr[i];
        s += v; s2 += v * v;
    }
    __shared__ float rs[8], rs2[8];
    #pragma unroll
    for (int o = 16; o > 0; o >>= 1) {
        s  += __shfl_xor_sync(0xffffffffu, s,  o);
        s2 += __shfl_xor_sync(0xffffffffu, s2, o);
    }
    if ((tid & 31) == 0) { rs[tid >> 5] = s; rs2[tid >> 5] = s2; }
    __syncthreads();
    if (tid < 32) {
        float a = (tid < 8) ? rs[tid]  : 0.f;
        float b = (tid < 8) ? rs2[tid] : 0.f;
        #pragma unroll
        for (int o = 4; o > 0; o >>= 1) {
            a += __shfl_xor_sync(0xffffffffu, a, o);
            b += __shfl_xor_sync(0xffffffffu, b, o);
        }
        if (tid == 0) { rs[0] = a; rs2[0] = b; }
    }
    __syncthreads();
    float mu  = rs[0] * (1.0f / Dm);
    float var = rs2[0] * (1.0f / Dm) - mu * mu;
    float inv = rsqrtf(var + 1e-5f);
    for (int i = tid; i < Dm; i += 256)
        orow[i] = (xr[i] - mu) * inv * gam[i] + bet[i];
}

// ---------------------------------------------------------------------------
// tf32 tensor-core GEMM, cp.async double-buffered.
// C[M,N] = A[M,K] * op(B); TB: B row-major [N,K]; else B row-major [K,N].
// Batched via blockIdx.z with element strides bA/bB/bC.
// EPI: 2 bias+residual, 3 bias+exact-gelu, 5 qkv scatter (bias=qb, res=vb),
//      6 exp(store)  [softmax numerator fused into scores GEMM].
// ---------------------------------------------------------------------------
template<int BM, int BN, int BK, int WM, int WN, bool TB, int EPI>
__global__ __launch_bounds__((BM/WM)*(BN/WN)*32)
void tgemm(const float* __restrict__ A, const float* __restrict__ B,
           float* __restrict__ C, int M, int N, int K,
           long bA, long bB, long bC,
           const float* __restrict__ bias, const float* __restrict__ res)
{
    constexpr int WARPS_M = BM / WM, WARPS_N = BN / WN;
    constexpr int NT = WARPS_M * WARPS_N * 32;
    constexpr int MI = WM / 16, NI = WN / 8, KI = BK / 8;
    constexpr int BKP = BK + 4, BNP = BN + 4;
    constexpr int BROWS = TB ? BN : BK;
    constexpr int BCOLS = TB ? BKP : BNP;

    __shared__ float As[2][BM][BKP];
    __shared__ float Bs[2][BROWS][BCOLS];

    int tid = threadIdx.x, lane = tid & 31, warp = tid >> 5;
    int wm = (warp % WARPS_M) * WM, wn = (warp / WARPS_M) * WN;
    int m0 = blockIdx.y * BM, n0 = blockIdx.x * BN;
    long z = blockIdx.z;
    const float* Ab = A + z * bA;
    const float* Bb = B + z * bB;

    uint32_t sA = (uint32_t)__cvta_generic_to_shared(&As[0][0][0]);
    uint32_t sB = (uint32_t)__cvta_generic_to_shared(&Bs[0][0][0]);

    auto loadTile = [&](int st, int k0) {
        for (int i = tid; i < BM * BK / 4; i += NT) {
            int r = i / (BK / 4), c = i % (BK / 4);
            uint32_t dst = sA + (uint32_t)(((st * BM + r) * BKP + c * 4) * 4);
            cp16(dst, Ab + (size_t)(m0 + r) * K + k0 + c * 4);
        }
        if (TB) {
            for (int i = tid; i < BN * BK / 4; i += NT) {
                int r = i / (BK / 4), c = i % (BK / 4);
                uint32_t dst = sB + (uint32_t)(((st * BROWS + r) * BCOLS + c * 4) * 4);
                cp16(dst, Bb + (size_t)(n0 + r) * K + k0 + c * 4);
            }
        } else {
            for (int i = tid; i < BK * BN / 4; i += NT) {
                int r = i / (BN / 4), c = i % (BN / 4);
                uint32_t dst = sB + (uint32_t)(((st * BROWS + r) * BCOLS + c * 4) * 4);
                cp16(dst, Bb + (size_t)(k0 + r) * N + n0 + c * 4);
            }
        }
        asm volatile("cp.async.commit_group;");
    };

    float acc[MI][NI][4] = {};
    int g = lane >> 2, tg = lane & 3;

    loadTile(0, 0);
    int NKT = K / BK;
    for (int kt = 0; kt < NKT; kt++) {
        int cur = kt & 1;
        if (kt + 1 < NKT) {
            loadTile((kt + 1) & 1, (kt + 1) * BK);
            asm volatile("cp.async.wait_group 1;");
        } else {
            asm volatile("cp.async.wait_group 0;");
        }
        __syncthreads();

        #pragma unroll
        for (int kk = 0; kk < KI; kk++) {
            uint32_t af[MI][4];
            uint32_t bf[NI][2];
            #pragma unroll
            for (int mi = 0; mi < MI; mi++) {
                int r0 = wm + mi * 16 + g;
                af[mi][0] = f2tf32(As[cur][r0    ][kk * 8 + tg    ]);
                af[mi][1] = f2tf32(As[cur][r0 + 8][kk * 8 + tg    ]);
                af[mi][2] = f2tf32(As[cur][r0    ][kk * 8 + tg + 4]);
                af[mi][3] = f2tf32(As[cur][r0 + 8][kk * 8 + tg + 4]);
            }
            #pragma unroll
            for (int ni = 0; ni < NI; ni++) {
                int cc = wn + ni * 8 + g;
                if (TB) {
                    bf[ni][0] = f2tf32(Bs[cur][cc][kk * 8 + tg    ]);
                    bf[ni][1] = f2tf32(Bs[cur][cc][kk * 8 + tg + 4]);
                } else {
                    bf[ni][0] = f2tf32(Bs[cur][kk * 8 + tg    ][cc]);
                    bf[ni][1] = f2tf32(Bs[cur][kk * 8 + tg + 4][cc]);
                }
            }
            #pragma unroll
            for (int mi = 0; mi < MI; mi++)
                #pragma unroll
                for (int ni = 0; ni < NI; ni++)
                    mma_tf32(acc[mi][ni], af[mi], bf[ni]);
        }
        __syncthreads();
    }

    // ---- epilogue ----
    #pragma unroll
    for (int mi = 0; mi < MI; mi++) {
        #pragma unroll
        for (int ni = 0; ni < NI; ni++) {
            #pragma unroll
            for (int half = 0; half < 2; half++) {
                int m = m0 + wm + mi * 16 + g + half * 8;
                float v0 = acc[mi][ni][half * 2 + 0];
                float v1 = acc[mi][ni][half * 2 + 1];
                int n = n0 + wn + ni * 8 + tg * 2;
                #pragma unroll
                for (int e = 0; e < 2; e++) {
                    float v = e ? v1 : v0;
                    int nn = n + e;
                    if (EPI == 2) {
                        C[(size_t)m * N + nn] = v + bias[nn] + res[(size_t)m * N + nn];
                    } else if (EPI == 3) {
                        float t = v + bias[nn];
                        C[(size_t)m * N + nn] =
                            0.5f * t * (1.f + erff(t * 0.70710678118654752f));
                    } else if (EPI == 5) {
                        int which = nn >> 10;
                        int r = nn & 1023;
                        int hh = r >> 6, hd = r & 63;
                        int bb = m >> 10, t = m & 1023;
                        size_t dst = (((size_t)bb * Hh + hh) * SEQm + t) * HDm + hd;
                        if (which == 0)      g_q[dst] = (v + bias[r]) * 0.125f;
                        else if (which == 1) g_k[dst] = v;
                        else                 g_v[dst] = v + res[r];
                    } else if (EPI == 6) {
                        C[z * bC + (size_t)m * N + nn] = __expf(v);
                    }
                }
            }
        }
    }
}

// ---------------------------------------------------------------------------
// attn PV: O[bh] = (P[bh] @ V[bh]) / rowsum(P[bh]); P = exp(scores) [1024,1024],
// V [1024,64]. Block = 128 q-rows of one bh. Row sums accumulated from the
// staged P tiles in a fixed order (deterministic), applied in the epilogue.
// Output scatter-stored to [b, t, (h,hd)] row-major [TOK, D].
// ---------------------------------------------------------------------------
__global__ __launch_bounds__(256)
void attn_pv(const float* __restrict__ P, const float* __restrict__ V,
             float* __restrict__ O)
{
    constexpr int BM = 128, BN = 64, BK = 16;
    constexpr int BKP = BK + 4, BNP = BN + 4;
    constexpr int MI = 2, NI = 4, KI = 2;   // WM=32, WN=32; 4x2 warps

    __shared__ float As[2][BM][BKP];
    __shared__ float Bs[2][BK][BNP];
    __shared__ float ssum[BM];

    int tid = threadIdx.x, lane = tid & 31, warp = tid >> 5;
    int g = lane >> 2, tg = lane & 3;
    int wm = (warp % 4) * 32, wn = (warp / 4) * 32;
    int m0 = blockIdx.y * BM;
    long z = blockIdx.x;                     // bh
    const float* Ab = P + z * (long)SEQm * SEQm;
    const float* Bb = V + z * (long)SEQm * HDm;

    uint32_t sA = (uint32_t)__cvta_generic_to_shared(&As[0][0][0]);
    uint32_t sB = (uint32_t)__cvta_generic_to_shared(&Bs[0][0][0]);

    auto loadTile = [&](int st, int k0) {
        #pragma unroll
        for (int i = tid; i < BM * BK / 4; i += 256) {
            int r = i / (BK / 4), c = i % (BK / 4);
            uint32_t dst = sA + (uint32_t)(((st * BM + r) * BKP + c * 4) * 4);
            cp16(dst, Ab + (size_t)(m0 + r) * SEQm + k0 + c * 4);
        }
        #pragma unroll
        for (int i = tid; i < BK * BN / 4; i += 256) {
            int r = i / (BN / 4), c = i % (BN / 4);
            uint32_t dst = sB + (uint32_t)(((st * BK + r) * BNP + c * 4) * 4);
            cp16(dst, Bb + (size_t)(k0 + r) * HDm + c * 4);
        }
        asm volatile("cp.async.commit_group;");
    };

    float acc[MI][NI][4] = {};
    float rsum = 0.f;
    int srow = tid & 127, shalf = (tid >> 7) * 8;

    loadTile(0, 0);
    constexpr int NKT = SEQm / BK;  // 64
    for (int kt = 0; kt < NKT; kt++) {
        int cur = kt & 1;
        if (kt + 1 < NKT) {
            loadTile((kt + 1) & 1, (kt + 1) * BK);
            asm volatile("cp.async.wait_group 1;");
        } else {
            asm volatile("cp.async.wait_group 0;");
        }
        __syncthreads();

        // row-sum contribution from this staged tile (fixed order, no atomics)
        {
            float4 a0 = *(const float4*)&As[cur][srow][shalf];
            float4 a1 = *(const float4*)&As[cur][srow][shalf + 4];
            rsum += (a0.x + a0.y) + (a0.z + a0.w) + (a1.x + a1.y) + (a1.z + a1.w);
        }

        #pragma unroll
        for (int kk = 0; kk < KI; kk++) {
            uint32_t af[MI][4];
            uint32_t bf[NI][2];
            #pragma unroll
            for (int mi = 0; mi < MI; mi++) {
                int r0 = wm + mi * 16 + g;
                af[mi][0] = f2tf32(As[cur][r0    ][kk * 8 + tg    ]);
                af[mi][1] = f2tf32(As[cur][r0 + 8][kk * 8 + tg    ]);
                af[mi][2] = f2tf32(As[cur][r0    ][kk * 8 + tg + 4]);
                af[mi][3] = f2tf32(As[cur][r0 + 8][kk * 8 + tg + 4]);
            }
            #pragma unroll
            for (int ni = 0; ni < NI; ni++) {
                int cc = wn + ni * 8 + g;
                bf[ni][0] = f2tf32(Bs[cur][kk * 8 + tg    ][cc]);
                bf[ni][1] = f2tf32(Bs[cur][kk * 8 + tg + 4][cc]);
            }
            #pragma unroll
            for (int mi = 0; mi < MI; mi++)
                #pragma unroll
                for (int ni = 0; ni < NI; ni++)
                    mma_tf32(acc[mi][ni], af[mi], bf[ni]);
        }
        __syncthreads();
    }

    // combine the two k-half row sums (deterministic order)
    if (tid < 128) ssum[srow] = rsum;
    __syncthreads();
    if (tid >= 128) ssum[srow] += rsum;
    __syncthreads();

    // epilogue: scale by 1/rowsum, scatter to [b, t, (h,hd)]
    int bb = (int)(z >> 4), hh = (int)(z & 15);
    #pragma unroll
    for (int mi = 0; mi < MI; mi++) {
        #pragma unroll
        for (int half = 0; half < 2; half++) {
            int ml = wm + mi * 16 + g + half * 8;
            float inv = 1.f / ssum[ml];
            size_t base = ((size_t)bb * SEQm + m0 + ml) * Dm + hh * HDm;
            #pragma unroll
            for (int ni = 0; ni < NI; ni++) {
                int c = wn + ni * 8 + tg * 2;
                float2 w = make_float2(acc[mi][ni][half * 2 + 0] * inv,
                                       acc[mi][ni][half * 2 + 1] * inv);
                *(float2*)&O[base + c] = w;
            }
        }
    }
}

// ---------------------------------------------------------------------------
extern "C" void kernel_launch(void* const* d_in, const int* in_sizes, int n_in,
                              void* d_out, int out_size)
{
    const float* x      = (const float*)d_in[0];
    const float* ln1_g  = (const float*)d_in[1];
    const float* ln1_b  = (const float*)d_in[2];
    const float* ln2_g  = (const float*)d_in[3];
    const float* ln2_b  = (const float*)d_in[4];
    const float* qkv_w  = (const float*)d_in[5];
    const float* q_bias = (const float*)d_in[6];
    const float* v_bias = (const float*)d_in[7];
    const float* proj_w = (const float*)d_in[8];
    const float* proj_b = (const float*)d_in[9];
    const float* fc1_w  = (const float*)d_in[10];
    const float* fc1_b  = (const float*)d_in[11];
    const float* fc2_w  = (const float*)d_in[12];
    const float* fc2_b  = (const float*)d_in[13];
    float* out = (float*)d_out;

    float *h, *q, *k, *v, *s, *o, *x1, *g;
    cudaGetSymbolAddress((void**)&h,  g_h);
    cudaGetSymbolAddress((void**)&q,  g_q);
    cudaGetSymbolAddress((void**)&k,  g_k);
    cudaGetSymbolAddress((void**)&v,  g_v);
    cudaGetSymbolAddress((void**)&s,  g_s);
    cudaGetSymbolAddress((void**)&o,  g_o);
    cudaGetSymbolAddress((void**)&x1, g_x1);
    cudaGetSymbolAddress((void**)&g,  g_g);

    // 1. LN1
    ln_kernel<<<TOKm, 256>>>(x, ln1_g, ln1_b, h);

    // 2. QKV = h @ qkv_w^T, fused scatter to q/k/v [B,H,N,HD] + biases + q-scale
    tgemm<128,128,16,64,32,true,5><<<dim3(3072/128, TOKm/128, 1), 256>>>(
        h, qkv_w, nullptr, TOKm, 3*Dm, Dm, 0, 0, 0, q_bias, v_bias);

    // 3. expS[bh] = exp(q[bh] @ k[bh]^T)  (K=64; exp fused in epilogue)
    tgemm<128,128,16,64,32,true,6><<<dim3(SEQm/128, SEQm/128, BHm), 256>>>(
        q, k, s, SEQm, SEQm, HDm,
        (long)SEQm*HDm, (long)SEQm*HDm, (long)SEQm*SEQm, nullptr, nullptr);

    // 4. o = (expS @ v) / rowsum(expS), scattered to [b,t,(h,hd)]
    attn_pv<<<dim3(BHm, SEQm/128), 256>>>(s, v, o);

    // 5. x1 = x + o @ proj_w^T + proj_b
    tgemm<128,128,16,64,32,true,2><<<dim3(Dm/128, TOKm/128, 1), 256>>>(
        o, proj_w, x1, TOKm, Dm, Dm, 0, 0, 0, proj_b, x);

    // 6. LN2
    ln_kernel<<<TOKm, 256>>>(x1, ln2_g, ln2_b, h);

    // 7. g = gelu(h @ fc1_w^T + fc1_b)
    tgemm<128,128,16,64,32,true,3><<<dim3(FFm/128, TOKm/128, 1), 256>>>(
        h, fc1_w, g, TOKm, FFm, Dm, 0, 0, 0, fc1_b, nullptr);

    // 8. out = x1 + g @ fc2_w^T + fc2_b
    tgemm<128,128,16,64,32,true,2><<<dim3(Dm/128, TOKm/128, 1), 256>>>(
        g, fc2_w, out, TOKm, Dm, FFm, 0, 0, 0, fc2_b, x1);
}

// round 9
// speedup vs baseline: 1.4787x; 1.0248x over previous
#include <cuda_runtime.h>
#include <math.h>
#include <stdint.h>

#define Dm 1024
#define Hh 16
#define HDm 64
#define FFm 4096
#define BATCHm 8
#define SEQm 1024
#define TOKm (BATCHm*SEQm)   /* 8192 */
#define BHm (BATCHm*Hh)      /* 128  */

static __device__ float g_h   [(size_t)TOKm*Dm];        // LN outputs (reused)
static __device__ float g_q   [(size_t)BHm*SEQm*HDm];
static __device__ float g_k   [(size_t)BHm*SEQm*HDm];
static __device__ float g_v   [(size_t)BHm*SEQm*HDm];
static __device__ float g_s   [(size_t)BHm*SEQm*SEQm]; // exp(scores)
static __device__ float g_o   [(size_t)TOKm*Dm];        // attn output [b,t,(h,hd)]
static __device__ float g_x1  [(size_t)TOKm*Dm];        // after attn residual
static __device__ float g_g   [(size_t)TOKm*FFm];       // gelu(fc1) out

// ---------------------------------------------------------------------------
// helpers
// ---------------------------------------------------------------------------
// HMMA.tf32 reads the tf32 bit-field from the b32 register; raw fp32 bits act
// as RZ-truncated tf32. Skipping cvt.rna.tf32 removes ~37% of inner-loop issue.
__device__ __forceinline__ uint32_t f2tf32(float f) {
    return __float_as_uint(f);
}
__device__ __forceinline__ void cp16(uint32_t dst, const void* src) {
    asm volatile("cp.async.cg.shared.global [%0], [%1], 16;" :: "r"(dst), "l"(src));
}
__device__ __forceinline__ void mma_tf32(float* c, const uint32_t* a, const uint32_t* b) {
    asm volatile(
        "mma.sync.aligned.m16n8k8.row.col.f32.tf32.tf32.f32 "
        "{%0,%1,%2,%3},{%4,%5,%6,%7},{%8,%9},{%0,%1,%2,%3};"
        : "+f"(c[0]), "+f"(c[1]), "+f"(c[2]), "+f"(c[3])
        : "r"(a[0]), "r"(a[1]), "r"(a[2]), "r"(a[3]), "r"(b[0]), "r"(b[1]));
}

// ---------------------------------------------------------------------------
// LayerNorm: one block per row (D=1024), 256 threads.
// ---------------------------------------------------------------------------
__global__ void ln_kernel(const float* __restrict__ x,
                          const float* __restrict__ gam,
                          const float* __restrict__ bet,
                          float* __restrict__ out)
{
    const float* xr = x + (size_t)blockIdx.x * Dm;
    float* orow     = out + (size_t)blockIdx.x * Dm;
    int tid = threadIdx.x;

    float s = 0.f, s2 = 0.f;
    for (int i = tid; i < Dm; i += 256) {
        float v = xr[i];
        s += v; s2 += v * v;
    }
    __shared__ float rs[8], rs2[8];
    #pragma unroll
    for (int o = 16; o > 0; o >>= 1) {
        s  += __shfl_xor_sync(0xffffffffu, s,  o);
        s2 += __shfl_xor_sync(0xffffffffu, s2, o);
    }
    if ((tid & 31) == 0) { rs[tid >> 5] = s; rs2[tid >> 5] = s2; }
    __syncthreads();
    if (tid < 32) {
        float a = (tid < 8) ? rs[tid]  : 0.f;
        float b = (tid < 8) ? rs2[tid] : 0.f;
        #pragma unroll
        for (int o = 4; o > 0; o >>= 1) {
            a += __shfl_xor_sync(0xffffffffu, a, o);
            b += __shfl_xor_sync(0xffffffffu, b, o);
        }
        if (tid == 0) { rs[0] = a; rs2[0] = b; }
    }
    __syncthreads();
    float mu  = rs[0] * (1.0f / Dm);
    float var = rs2[0] * (1.0f / Dm) - mu * mu;
    float inv = rsqrtf(var + 1e-5f);
    for (int i = tid; i < Dm; i += 256)
        orow[i] = (xr[i] - mu) * inv * gam[i] + bet[i];
}

// ---------------------------------------------------------------------------
// tf32 tensor-core GEMM, cp.async double-buffered.
// C[M,N] = A[M,K] * op(B); TB: B row-major [N,K]; else B row-major [K,N].
// Batched via blockIdx.z with element strides bA/bB/bC.
// EPI: 2 bias+residual, 3 bias+exact-gelu, 5 qkv scatter (bias=qb, res=vb),
//      6 exp(store)  [softmax numerator fused into scores GEMM].
// ---------------------------------------------------------------------------
template<int BM, int BN, int BK, int WM, int WN, bool TB, int EPI>
__global__ __launch_bounds__((BM/WM)*(BN/WN)*32)
void tgemm(const float* __restrict__ A, const float* __restrict__ B,
           float* __restrict__ C, int M, int N, int K,
           long bA, long bB, long bC,
           const float* __restrict__ bias, const float* __restrict__ res)
{
    constexpr int WARPS_M = BM / WM, WARPS_N = BN / WN;
    constexpr int NT = WARPS_M * WARPS_N * 32;
    constexpr int MI = WM / 16, NI = WN / 8, KI = BK / 8;
    constexpr int BKP = BK + 4, BNP = BN + 4;
    constexpr int BROWS = TB ? BN : BK;
    constexpr int BCOLS = TB ? BKP : BNP;

    __shared__ float As[2][BM][BKP];
    __shared__ float Bs[2][BROWS][BCOLS];

    int tid = threadIdx.x, lane = tid & 31, warp = tid >> 5;
    int wm = (warp % WARPS_M) * WM, wn = (warp / WARPS_M) * WN;
    int m0 = blockIdx.y * BM, n0 = blockIdx.x * BN;
    long z = blockIdx.z;
    const float* Ab = A + z * bA;
    const float* Bb = B + z * bB;

    uint32_t sA = (uint32_t)__cvta_generic_to_shared(&As[0][0][0]);
    uint32_t sB = (uint32_t)__cvta_generic_to_shared(&Bs[0][0][0]);

    auto loadTile = [&](int st, int k0) {
        for (int i = tid; i < BM * BK / 4; i += NT) {
            int r = i / (BK / 4), c = i % (BK / 4);
            uint32_t dst = sA + (uint32_t)(((st * BM + r) * BKP + c * 4) * 4);
            cp16(dst, Ab + (size_t)(m0 + r) * K + k0 + c * 4);
        }
        if (TB) {
            for (int i = tid; i < BN * BK / 4; i += NT) {
                int r = i / (BK / 4), c = i % (BK / 4);
                uint32_t dst = sB + (uint32_t)(((st * BROWS + r) * BCOLS + c * 4) * 4);
                cp16(dst, Bb + (size_t)(n0 + r) * K + k0 + c * 4);
            }
        } else {
            for (int i = tid; i < BK * BN / 4; i += NT) {
                int r = i / (BN / 4), c = i % (BN / 4);
                uint32_t dst = sB + (uint32_t)(((st * BROWS + r) * BCOLS + c * 4) * 4);
                cp16(dst, Bb + (size_t)(k0 + r) * N + n0 + c * 4);
            }
        }
        asm volatile("cp.async.commit_group;");
    };

    float acc[MI][NI][4] = {};
    int g = lane >> 2, tg = lane & 3;

    loadTile(0, 0);
    int NKT = K / BK;
    for (int kt = 0; kt < NKT; kt++) {
        int cur = kt & 1;
        if (kt + 1 < NKT) {
            loadTile((kt + 1) & 1, (kt + 1) * BK);
            asm volatile("cp.async.wait_group 1;");
        } else {
            asm volatile("cp.async.wait_group 0;");
        }
        __syncthreads();

        #pragma unroll
        for (int kk = 0; kk < KI; kk++) {
            uint32_t af[MI][4];
            uint32_t bf[NI][2];
            #pragma unroll
            for (int mi = 0; mi < MI; mi++) {
                int r0 = wm + mi * 16 + g;
                af[mi][0] = f2tf32(As[cur][r0    ][kk * 8 + tg    ]);
                af[mi][1] = f2tf32(As[cur][r0 + 8][kk * 8 + tg    ]);
                af[mi][2] = f2tf32(As[cur][r0    ][kk * 8 + tg + 4]);
                af[mi][3] = f2tf32(As[cur][r0 + 8][kk * 8 + tg + 4]);
            }
            #pragma unroll
            for (int ni = 0; ni < NI; ni++) {
                int cc = wn + ni * 8 + g;
                if (TB) {
                    bf[ni][0] = f2tf32(Bs[cur][cc][kk * 8 + tg    ]);
                    bf[ni][1] = f2tf32(Bs[cur][cc][kk * 8 + tg + 4]);
                } else {
                    bf[ni][0] = f2tf32(Bs[cur][kk * 8 + tg    ][cc]);
                    bf[ni][1] = f2tf32(Bs[cur][kk * 8 + tg + 4][cc]);
                }
            }
            #pragma unroll
            for (int mi = 0; mi < MI; mi++)
                #pragma unroll
                for (int ni = 0; ni < NI; ni++)
                    mma_tf32(acc[mi][ni], af[mi], bf[ni]);
        }
        __syncthreads();
    }

    // ---- epilogue ----
    #pragma unroll
    for (int mi = 0; mi < MI; mi++) {
        #pragma unroll
        for (int ni = 0; ni < NI; ni++) {
            #pragma unroll
            for (int half = 0; half < 2; half++) {
                int m = m0 + wm + mi * 16 + g + half * 8;
                float v0 = acc[mi][ni][half * 2 + 0];
                float v1 = acc[mi][ni][half * 2 + 1];
                int n = n0 + wn + ni * 8 + tg * 2;
                #pragma unroll
                for (int e = 0; e < 2; e++) {
                    float v = e ? v1 : v0;
                    int nn = n + e;
                    if (EPI == 2) {
                        C[(size_t)m * N + nn] = v + bias[nn] + res[(size_t)m * N + nn];
                    } else if (EPI == 3) {
                        float t = v + bias[nn];
                        C[(size_t)m * N + nn] =
                            0.5f * t * (1.f + erff(t * 0.70710678118654752f));
                    } else if (EPI == 5) {
                        int which = nn >> 10;
                        int r = nn & 1023;
                        int hh = r >> 6, hd = r & 63;
                        int bb = m >> 10, t = m & 1023;
                        size_t dst = (((size_t)bb * Hh + hh) * SEQm + t) * HDm + hd;
                        if (which == 0)      g_q[dst] = (v + bias[r]) * 0.125f;
                        else if (which == 1) g_k[dst] = v;
                        else                 g_v[dst] = v + res[r];
                    } else if (EPI == 6) {
                        C[z * bC + (size_t)m * N + nn] = __expf(v);
                    }
                }
            }
        }
    }
}

// ---------------------------------------------------------------------------
// attn PV: O[bh] = (P[bh] @ V[bh]) / rowsum(P[bh]); P = exp(scores) [1024,1024],
// V [1024,64]. Block = 128 q-rows of one bh. Row sums accumulated from the
// staged P tiles in a fixed order (deterministic), applied in the epilogue.
// Output scatter-stored to [b, t, (h,hd)] row-major [TOK, D].
// ---------------------------------------------------------------------------
__global__ __launch_bounds__(256, 3)
void attn_pv(const float* __restrict__ P, const float* __restrict__ V,
             float* __restrict__ O)
{
    constexpr int BM = 128, BN = 64, BK = 16;
    constexpr int BKP = BK + 4, BNP = BN + 4;
    constexpr int MI = 2, NI = 4, KI = 2;   // WM=32, WN=32; 4x2 warps

    __shared__ float As[2][BM][BKP];
    __shared__ float Bs[2][BK][BNP];
    __shared__ float ssum[BM];

    int tid = threadIdx.x, lane = tid & 31, warp = tid >> 5;
    int g = lane >> 2, tg = lane & 3;
    int wm = (warp % 4) * 32, wn = (warp / 4) * 32;
    int m0 = blockIdx.y * BM;
    long z = blockIdx.x;                     // bh
    const float* Ab = P + z * (long)SEQm * SEQm;
    const float* Bb = V + z * (long)SEQm * HDm;

    uint32_t sA = (uint32_t)__cvta_generic_to_shared(&As[0][0][0]);
    uint32_t sB = (uint32_t)__cvta_generic_to_shared(&Bs[0][0][0]);

    auto loadTile = [&](int st, int k0) {
        #pragma unroll
        for (int i = tid; i < BM * BK / 4; i += 256) {
            int r = i / (BK / 4), c = i % (BK / 4);
            uint32_t dst = sA + (uint32_t)(((st * BM + r) * BKP + c * 4) * 4);
            cp16(dst, Ab + (size_t)(m0 + r) * SEQm + k0 + c * 4);
        }
        #pragma unroll
        for (int i = tid; i < BK * BN / 4; i += 256) {
            int r = i / (BN / 4), c = i % (BN / 4);
            uint32_t dst = sB + (uint32_t)(((st * BK + r) * BNP + c * 4) * 4);
            cp16(dst, Bb + (size_t)(k0 + r) * HDm + c * 4);
        }
        asm volatile("cp.async.commit_group;");
    };

    float acc[MI][NI][4] = {};
    float rsum = 0.f;
    int srow = tid & 127, shalf = (tid >> 7) * 8;

    loadTile(0, 0);
    constexpr int NKT = SEQm / BK;  // 64
    for (int kt = 0; kt < NKT; kt++) {
        int cur = kt & 1;
        if (kt + 1 < NKT) {
            loadTile((kt + 1) & 1, (kt + 1) * BK);
            asm volatile("cp.async.wait_group 1;");
        } else {
            asm volatile("cp.async.wait_group 0;");
        }
        __syncthreads();

        // row-sum contribution from this staged tile (fixed order, no atomics)
        {
            float4 a0 = *(const float4*)&As[cur][srow][shalf];
            float4 a1 = *(const float4*)&As[cur][srow][shalf + 4];
            rsum += (a0.x + a0.y) + (a0.z + a0.w) + (a1.x + a1.y) + (a1.z + a1.w);
        }

        #pragma unroll
        for (int kk = 0; kk < KI; kk++) {
            uint32_t af[MI][4];
            uint32_t bf[NI][2];
            #pragma unroll
            for (int mi = 0; mi < MI; mi++) {
                int r0 = wm + mi * 16 + g;
                af[mi][0] = f2tf32(As[cur][r0    ][kk * 8 + tg    ]);
                af[mi][1] = f2tf32(As[cur][r0 + 8][kk * 8 + tg    ]);
                af[mi][2] = f2tf32(As[cur][r0    ][kk * 8 + tg + 4]);
                af[mi][3] = f2tf32(As[cur][r0 + 8][kk * 8 + tg + 4]);
            }
            #pragma unroll
            for (int ni = 0; ni < NI; ni++) {
                int cc = wn + ni * 8 + g;
                bf[ni][0] = f2tf32(Bs[cur][kk * 8 + tg    ][cc]);
                bf[ni][1] = f2tf32(Bs[cur][kk * 8 + tg + 4][cc]);
            }
            #pragma unroll
            for (int mi = 0; mi < MI; mi++)
                #pragma unroll
                for (int ni = 0; ni < NI; ni++)
                    mma_tf32(acc[mi][ni], af[mi], bf[ni]);
        }
        __syncthreads();
    }

    // combine the two k-half row sums (deterministic order)
    if (tid < 128) ssum[srow] = rsum;
    __syncthreads();
    if (tid >= 128) ssum[srow] += rsum;
    __syncthreads();

    // epilogue: scale by 1/rowsum, scatter to [b, t, (h,hd)]
    int bb = (int)(z >> 4), hh = (int)(z & 15);
    #pragma unroll
    for (int mi = 0; mi < MI; mi++) {
        #pragma unroll
        for (int half = 0; half < 2; half++) {
            int ml = wm + mi * 16 + g + half * 8;
            float inv = 1.f / ssum[ml];
            size_t base = ((size_t)bb * SEQm + m0 + ml) * Dm + hh * HDm;
            #pragma unroll
            for (int ni = 0; ni < NI; ni++) {
                int c = wn + ni * 8 + tg * 2;
                float2 w = make_float2(acc[mi][ni][half * 2 + 0] * inv,
                                       acc[mi][ni][half * 2 + 1] * inv);
                *(float2*)&O[base + c] = w;
            }
        }
    }
}

// ---------------------------------------------------------------------------
extern "C" void kernel_launch(void* const* d_in, const int* in_sizes, int n_in,
                              void* d_out, int out_size)
{
    const float* x      = (const float*)d_in[0];
    const float* ln1_g  = (const float*)d_in[1];
    const float* ln1_b  = (const float*)d_in[2];
    const float* ln2_g  = (const float*)d_in[3];
    const float* ln2_b  = (const float*)d_in[4];
    const float* qkv_w  = (const float*)d_in[5];
    const float* q_bias = (const float*)d_in[6];
    const float* v_bias = (const float*)d_in[7];
    const float* proj_w = (const float*)d_in[8];
    const float* proj_b = (const float*)d_in[9];
    const float* fc1_w  = (const float*)d_in[10];
    const float* fc1_b  = (const float*)d_in[11];
    const float* fc2_w  = (const float*)d_in[12];
    const float* fc2_b  = (const float*)d_in[13];
    float* out = (float*)d_out;

    float *h, *q, *k, *v, *s, *o, *x1, *g;
    cudaGetSymbolAddress((void**)&h,  g_h);
    cudaGetSymbolAddress((void**)&q,  g_q);
    cudaGetSymbolAddress((void**)&k,  g_k);
    cudaGetSymbolAddress((void**)&v,  g_v);
    cudaGetSymbolAddress((void**)&s,  g_s);
    cudaGetSymbolAddress((void**)&o,  g_o);
    cudaGetSymbolAddress((void**)&x1, g_x1);
    cudaGetSymbolAddress((void**)&g,  g_g);

    // 1. LN1
    ln_kernel<<<TOKm, 256>>>(x, ln1_g, ln1_b, h);

    // 2. QKV = h @ qkv_w^T, fused scatter to q/k/v [B,H,N,HD] + biases + q-scale
    tgemm<128,128,16,64,32,true,5><<<dim3(3072/128, TOKm/128, 1), 256>>>(
        h, qkv_w, nullptr, TOKm, 3*Dm, Dm, 0, 0, 0, q_bias, v_bias);

    // 3. expS[bh] = exp(q[bh] @ k[bh]^T)  (K=64; exp fused in epilogue)
    tgemm<128,128,16,64,32,true,6><<<dim3(SEQm/128, SEQm/128, BHm), 256>>>(
        q, k, s, SEQm, SEQm, HDm,
        (long)SEQm*HDm, (long)SEQm*HDm, (long)SEQm*SEQm, nullptr, nullptr);

    // 4. o = (expS @ v) / rowsum(expS), scattered to [b,t,(h,hd)]
    attn_pv<<<dim3(BHm, SEQm/128), 256>>>(s, v, o);

    // 5. x1 = x + o @ proj_w^T + proj_b
    tgemm<128,128,16,64,32,true,2><<<dim3(Dm/128, TOKm/128, 1), 256>>>(
        o, proj_w, x1, TOKm, Dm, Dm, 0, 0, 0, proj_b, x);

    // 6. LN2
    ln_kernel<<<TOKm, 256>>>(x1, ln2_g, ln2_b, h);

    // 7. g = gelu(h @ fc1_w^T + fc1_b)
    tgemm<128,128,16,64,32,true,3><<<dim3(FFm/128, TOKm/128, 1), 256>>>(
        h, fc1_w, g, TOKm, FFm, Dm, 0, 0, 0, fc1_b, nullptr);

    // 8. out = x1 + g @ fc2_w^T + fc2_b
    tgemm<128,128,16,64,32,true,2><<<dim3(Dm/128, TOKm/128, 1), 256>>>(
        g, fc2_w, out, TOKm, Dm, FFm, 0, 0, 0, fc2_b, x1);
}